// round 4
// baseline (speedup 1.0000x reference)
#include <cuda_runtime.h>
#include <cstdint>

// Problem shape (fixed by the dataset):
//   x:       (4, 2048, 4096) fp32  -> M=8192, K=4096 row-major
//   qweight: (512, 11008)   int32  -> K/8 rows, 8 int4 nibbles per int32 along K
//   scales:  (32, 11008)    fp32   -> per-group(128) per-out-channel
//   out:     (4, 2048, 11008) fp32 -> M x N
static constexpr int M_DIM = 8192;
static constexpr int K_DIM = 4096;
static constexpr int N_DIM = 11008;

static constexpr int BM = 128;
static constexpr int BN = 128;
static constexpr int BK = 16;
static constexpr int TM = 8;
static constexpr int TN = 8;
static constexpr int NTHREADS = (BM / TM) * (BN / TN);  // 256

__global__ __launch_bounds__(NTHREADS, 2)
void int4_gemm_f32_kernel(const float* __restrict__ X,
                          const int*   __restrict__ QW,
                          const float* __restrict__ SC,
                          float*       __restrict__ C)
{
    // As transposed (k-major) with +4 padding to break bank conflicts on the
    // transposed stores; Bs holds the dequantized int4 tile.
    __shared__ float As[BK][BM + 4];
    __shared__ float Bs[BK][BN];

    const int tid = threadIdx.x;
    const int tx  = tid & 15;   // n direction (16)
    const int ty  = tid >> 4;   // m direction (16)

    const int m0 = blockIdx.y * BM;
    const int n0 = blockIdx.x * BN;

    // B-tile dequant mapping: one int32 (8 nibbles = 8 k-values) per thread.
    // BK=16 -> 2 qweight rows x 128 columns = 256 int32 = 256 threads.
    const int bn = tid & (BN - 1);  // 0..127
    const int br = tid >> 7;        // 0..1

    float acc[TM][TN];
    #pragma unroll
    for (int i = 0; i < TM; i++)
        #pragma unroll
        for (int j = 0; j < TN; j++) acc[i][j] = 0.0f;

    for (int k0 = 0; k0 < K_DIM; k0 += BK) {
        // ---- Load A tile (BM x BK) as float4, store transposed -----------
        #pragma unroll
        for (int p = 0; p < 2; p++) {
            int f   = tid + p * NTHREADS;   // 0..511
            int row = f >> 2;               // 0..127 (m within tile)
            int kk  = (f & 3) << 2;         // 0,4,8,12
            float4 v = *reinterpret_cast<const float4*>(
                &X[(size_t)(m0 + row) * K_DIM + k0 + kk]);
            As[kk + 0][row] = v.x;
            As[kk + 1][row] = v.y;
            As[kk + 2][row] = v.z;
            As[kk + 3][row] = v.w;
        }

        // ---- Dequantize B tile (BK x BN) into SMEM ------------------------
        // BK=16 never crosses a group boundary (16 | 128), so one scale per
        // (tile, column).
        {
            int krow = (k0 >> 3) + br;  // qweight row index
            unsigned int q = (unsigned int)QW[(size_t)krow * N_DIM + n0 + bn];
            float s = SC[(size_t)(k0 >> 7) * N_DIM + n0 + bn];
            #pragma unroll
            for (int j = 0; j < 8; j++) {
                Bs[br * 8 + j][bn] =
                    ((float)((q >> (4 * j)) & 15u) - 8.0f) * s;
            }
        }
        __syncthreads();

        // ---- Rank-1 updates over the K slice ------------------------------
        #pragma unroll
        for (int k = 0; k < BK; k++) {
            float a[TM], b[TN];
            #pragma unroll
            for (int i = 0; i < TM; i++) a[i] = As[k][ty * TM + i];
            #pragma unroll
            for (int j = 0; j < TN; j++) b[j] = Bs[k][tx * TN + j];
            #pragma unroll
            for (int i = 0; i < TM; i++)
                #pragma unroll
                for (int j = 0; j < TN; j++)
                    acc[i][j] = fmaf(a[i], b[j], acc[i][j]);
        }
        __syncthreads();
    }

    // ---- Writeback: 8x8 per thread, float4 stores -------------------------
    #pragma unroll
    for (int i = 0; i < TM; i++) {
        size_t off = (size_t)(m0 + ty * TM + i) * N_DIM + n0 + tx * TN;
        float4 v0 = make_float4(acc[i][0], acc[i][1], acc[i][2], acc[i][3]);
        float4 v1 = make_float4(acc[i][4], acc[i][5], acc[i][6], acc[i][7]);
        *reinterpret_cast<float4*>(&C[off])     = v0;
        *reinterpret_cast<float4*>(&C[off + 4]) = v1;
    }
}

extern "C" void kernel_launch(void* const* d_in, const int* in_sizes, int n_in,
                              void* d_out, int out_size)
{
    const float* x  = (const float*)d_in[0];
    const int*   qw = (const int*)d_in[1];
    const float* sc = (const float*)d_in[2];
    float*       out = (float*)d_out;

    dim3 grid(N_DIM / BN, M_DIM / BM);  // (86, 64)
    int4_gemm_f32_kernel<<<grid, NTHREADS>>>(x, qw, sc, out);
}

// round 5
// speedup vs baseline: 2.6225x; 2.6225x over previous
#include <cuda_runtime.h>
#include <cstdint>

// Problem shape (fixed by the dataset):
//   x:       (4, 2048, 4096) fp32  -> M=8192, K=4096 row-major
//   qweight: (512, 11008)   int32  -> 8 int4 nibbles per int32 along K
//   scales:  (32, 11008)    fp32   -> per-group(128) per-out-channel
//   out:     (4, 2048, 11008) fp32
static constexpr int M_DIM = 8192;
static constexpr int K_DIM = 4096;
static constexpr int N_DIM = 11008;

static constexpr int BM = 128;
static constexpr int BN = 256;
static constexpr int BK = 16;
static constexpr int NTH = 256;   // 8 warps, 2 (m) x 4 (n); warp tile 64x64

// SMEM strides chosen for conflict-free mma fragment loads:
//  As[m][k]: stride 20  -> lds bank = (20g + t) % 32, all 32 distinct
//  Bs[k][n]: stride 264 -> lds bank = (8t + g) % 32, all 32 distinct
static constexpr int AS_STRIDE = BK + 4;   // 20
static constexpr int BS_STRIDE = BN + 8;   // 264

__device__ __forceinline__ uint32_t f2tf32(float f) {
    uint32_t r;
    asm("cvt.rna.tf32.f32 %0, %1;" : "=r"(r) : "f"(f));
    return r;
}

__device__ __forceinline__ void mma_tf32(float c[4],
                                         uint32_t a0, uint32_t a1,
                                         uint32_t a2, uint32_t a3,
                                         uint32_t b0, uint32_t b1)
{
    asm volatile(
        "mma.sync.aligned.m16n8k8.row.col.f32.tf32.tf32.f32 "
        "{%0,%1,%2,%3}, {%4,%5,%6,%7}, {%8,%9}, {%0,%1,%2,%3};\n"
        : "+f"(c[0]), "+f"(c[1]), "+f"(c[2]), "+f"(c[3])
        : "r"(a0), "r"(a1), "r"(a2), "r"(a3), "r"(b0), "r"(b1));
}

__global__ __launch_bounds__(NTH, 1)
void int4_gemm_tf32_kernel(const float* __restrict__ X,
                           const int*   __restrict__ QW,
                           const float* __restrict__ SC,
                           float*       __restrict__ C)
{
    __shared__ uint32_t As[BM * AS_STRIDE];   // 10.0 KB
    __shared__ uint32_t Bs[BK * BS_STRIDE];   // 16.5 KB

    const int tid  = threadIdx.x;
    const int wid  = tid >> 5;
    const int lane = tid & 31;
    const int g    = lane >> 2;   // groupID
    const int t    = lane & 3;    // threadID in group

    const int wm = wid >> 2;      // 0..1  (m)
    const int wn = wid & 3;       // 0..3  (n)

    const int m0 = blockIdx.y * BM;
    const int n0 = blockIdx.x * BN;

    // ---- accumulators: warp 64x64 -> 4 m-tiles x 8 n-tiles x 4 regs ------
    float acc[4][8][4];
    #pragma unroll
    for (int i = 0; i < 4; i++)
        #pragma unroll
        for (int j = 0; j < 8; j++)
            #pragma unroll
            for (int r = 0; r < 4; r++) acc[i][j][r] = 0.0f;

    // ---- global-load staging mapping --------------------------------------
    // A: each thread loads 8 consecutive k of one row: row=tid>>1, kcol=(tid&1)*8
    const int arow = tid >> 1;
    const int acol = (tid & 1) * 8;
    const float* Xrow = X + (size_t)(m0 + arow) * K_DIM + acol;

    // B: each thread owns column n0+tid, qweight rows (k0/8) and (k0/8)+1
    const int*   QWc = QW + n0 + tid;
    const float* SCc = SC + n0 + tid;

    float4 va0, va1;
    int    q0, q1;
    float  s;

    // prologue: stage tile k0=0
    va0 = *reinterpret_cast<const float4*>(Xrow + 0);
    va1 = *reinterpret_cast<const float4*>(Xrow + 4);
    q0  = QWc[(size_t)0 * N_DIM];
    q1  = QWc[(size_t)1 * N_DIM];
    s   = SCc[0];

    for (int k0 = 0; k0 < K_DIM; k0 += BK) {
        __syncthreads();   // previous tile's consumers done

        // ---- commit staged tile to SMEM (tf32-rounded) --------------------
        {
            uint32_t* ap = &As[arow * AS_STRIDE + acol];
            ap[0] = f2tf32(va0.x); ap[1] = f2tf32(va0.y);
            ap[2] = f2tf32(va0.z); ap[3] = f2tf32(va0.w);
            ap[4] = f2tf32(va1.x); ap[5] = f2tf32(va1.y);
            ap[6] = f2tf32(va1.z); ap[7] = f2tf32(va1.w);

            unsigned int uq0 = (unsigned int)q0, uq1 = (unsigned int)q1;
            #pragma unroll
            for (int j = 0; j < 8; j++) {
                float w0 = ((float)((uq0 >> (4 * j)) & 15u) - 8.0f) * s;
                float w1 = ((float)((uq1 >> (4 * j)) & 15u) - 8.0f) * s;
                Bs[(j)     * BS_STRIDE + tid] = f2tf32(w0);
                Bs[(j + 8) * BS_STRIDE + tid] = f2tf32(w1);
            }
        }
        __syncthreads();   // tile ready

        // ---- stage next tile (overlaps with MMA below) ---------------------
        if (k0 + BK < K_DIM) {
            const float* xp = Xrow + (k0 + BK);
            va0 = *reinterpret_cast<const float4*>(xp + 0);
            va1 = *reinterpret_cast<const float4*>(xp + 4);
            int krow = (k0 + BK) >> 3;
            q0 = QWc[(size_t)(krow)     * N_DIM];
            q1 = QWc[(size_t)(krow + 1) * N_DIM];
            s  = SCc[(size_t)((k0 + BK) >> 7) * N_DIM];
        }

        // ---- compute: 2 x k8 steps, 64 MMAs per warp -----------------------
        #pragma unroll
        for (int kk = 0; kk < 2; kk++) {
            const int kb = kk * 8;

            uint32_t a[4][4];
            #pragma unroll
            for (int i = 0; i < 4; i++) {
                int mrow = wm * 64 + i * 16;
                a[i][0] = As[(mrow + g)     * AS_STRIDE + kb + t];
                a[i][1] = As[(mrow + g + 8) * AS_STRIDE + kb + t];
                a[i][2] = As[(mrow + g)     * AS_STRIDE + kb + t + 4];
                a[i][3] = As[(mrow + g + 8) * AS_STRIDE + kb + t + 4];
            }

            uint32_t b[8][2];
            #pragma unroll
            for (int j = 0; j < 8; j++) {
                int ncol = wn * 64 + j * 8 + g;
                b[j][0] = Bs[(kb + t)     * BS_STRIDE + ncol];
                b[j][1] = Bs[(kb + t + 4) * BS_STRIDE + ncol];
            }

            #pragma unroll
            for (int i = 0; i < 4; i++)
                #pragma unroll
                for (int j = 0; j < 8; j++)
                    mma_tf32(acc[i][j],
                             a[i][0], a[i][1], a[i][2], a[i][3],
                             b[j][0], b[j][1]);
        }
    }

    // ---- writeback ---------------------------------------------------------
    #pragma unroll
    for (int i = 0; i < 4; i++) {
        int row = m0 + wm * 64 + i * 16 + g;
        #pragma unroll
        for (int j = 0; j < 8; j++) {
            int col = n0 + wn * 64 + j * 8 + 2 * t;
            float2 v01 = make_float2(acc[i][j][0], acc[i][j][1]);
            float2 v23 = make_float2(acc[i][j][2], acc[i][j][3]);
            *reinterpret_cast<float2*>(&C[(size_t)row       * N_DIM + col]) = v01;
            *reinterpret_cast<float2*>(&C[(size_t)(row + 8) * N_DIM + col]) = v23;
        }
    }
}

extern "C" void kernel_launch(void* const* d_in, const int* in_sizes, int n_in,
                              void* d_out, int out_size)
{
    const float* x   = (const float*)d_in[0];
    const int*   qw  = (const int*)d_in[1];
    const float* sc  = (const float*)d_in[2];
    float*       out = (float*)d_out;

    dim3 grid(N_DIM / BN, M_DIM / BM);  // (43, 64)
    int4_gemm_tf32_kernel<<<grid, NTH>>>(x, qw, sc, out);
}

// round 7
// speedup vs baseline: 3.1997x; 1.2201x over previous
#include <cuda_runtime.h>
#include <cstdint>

// Problem shape (fixed by the dataset):
//   x:       (4, 2048, 4096) fp32  -> M=8192, K=4096 row-major
//   qweight: (512, 11008)   int32  -> 8 int4 nibbles per int32 along K
//   scales:  (32, 11008)    fp32   -> per-group(128) per-out-channel
//   out:     (4, 2048, 11008) fp32
static constexpr int M_DIM = 8192;
static constexpr int K_DIM = 4096;
static constexpr int N_DIM = 11008;

static constexpr int BM = 128;
static constexpr int BN = 256;
static constexpr int BK = 32;
static constexpr int NTH = 256;              // 8 warps, 2(m) x 4(n), warp tile 64x64
static constexpr int K_ITERS = K_DIM / BK;   // 128

// SMEM strides for conflict-free fragment loads:
//  As[m][k] stride 36 -> lds bank (4g + t) % 32, all distinct
//  Bs[k][n] stride 264 -> lds bank (8t + g) % 32, all distinct
static constexpr int AS_STRIDE = BK + 4;     // 36 floats (144B rows, 16B aligned)
static constexpr int BS_STRIDE = BN + 8;     // 264
static constexpr int A_ELEMS = BM * AS_STRIDE;   // 4608 floats / buffer
static constexpr int B_ELEMS = BK * BS_STRIDE;   // 8448 floats / buffer
static constexpr int SMEM_BYTES = 2 * (A_ELEMS + B_ELEMS) * 4;  // 104448

__device__ __forceinline__ uint32_t smem_u32(const void* p) {
    uint32_t a;
    asm("{ .reg .u64 t; cvta.to.shared.u64 t, %1; cvt.u32.u64 %0, t; }"
        : "=r"(a) : "l"(p));
    return a;
}

__device__ __forceinline__ void cp16(uint32_t dst_smem, const void* src) {
    asm volatile("cp.async.cg.shared.global [%0], [%1], 16;"
                 :: "r"(dst_smem), "l"(src));
}

// Round-to-nearest fp32 -> tf32 in the integer domain (HMMA ignores low 13 bits)
__device__ __forceinline__ float rn_tf32(float w) {
    return __uint_as_float(__float_as_uint(w) + 0x1000u);
}

__device__ __forceinline__ void mma_tf32(float c[4],
                                         uint32_t a0, uint32_t a1,
                                         uint32_t a2, uint32_t a3,
                                         uint32_t b0, uint32_t b1)
{
    asm volatile(
        "mma.sync.aligned.m16n8k8.row.col.f32.tf32.tf32.f32 "
        "{%0,%1,%2,%3}, {%4,%5,%6,%7}, {%8,%9}, {%0,%1,%2,%3};\n"
        : "+f"(c[0]), "+f"(c[1]), "+f"(c[2]), "+f"(c[3])
        : "r"(a0), "r"(a1), "r"(a2), "r"(a3), "r"(b0), "r"(b1));
}

__global__ __launch_bounds__(NTH, 1)
void int4_gemm_tf32_db_kernel(const float* __restrict__ X,
                              const int*   __restrict__ QW,
                              const float* __restrict__ SC,
                              float*       __restrict__ C)
{
    extern __shared__ float smem[];
    float* As = smem;                  // 2 x A_ELEMS
    float* Bs = smem + 2 * A_ELEMS;    // 2 x B_ELEMS
    const uint32_t As_sm = smem_u32(As);

    const int tid  = threadIdx.x;
    const int wid  = tid >> 5;
    const int lane = tid & 31;
    const int g    = lane >> 2;        // 0..7
    const int t    = lane & 3;         // 0..3
    const int wm   = wid >> 2;         // 0..1
    const int wn   = wid & 3;          // 0..3

    const int m0 = blockIdx.y * BM;
    const int n0 = blockIdx.x * BN;

    // ---- accumulators: warp 64x64 -> 4 x 8 x 4 regs ------------------------
    float acc[4][8][4];
    #pragma unroll
    for (int i = 0; i < 4; i++)
        #pragma unroll
        for (int j = 0; j < 8; j++)
            #pragma unroll
            for (int r = 0; r < 4; r++) acc[i][j][r] = 0.0f;

    // ---- producer mappings --------------------------------------------------
    // A: thread -> row tid>>1 (0..127), half tid&1 (16 floats = 4 x cp16)
    const int arow  = tid >> 1;
    const int ahalf = (tid & 1) * 16;
    const float* Xrow = X + (size_t)(m0 + arow) * K_DIM + ahalf;
    const uint32_t a_dst0 = As_sm + (uint32_t)(arow * AS_STRIDE + ahalf) * 4u;

    // B: thread -> output column n0+tid; 4 qweight rows per tile (BK=32)
    const int*   QWp = QW + n0 + tid;
    const float* SCp = SC + n0 + tid;

    int   qv[4];
    float s;

    // ---- prologue: stage + commit tile 0 ------------------------------------
    {
        #pragma unroll
        for (int c = 0; c < 4; c++)
            cp16(a_dst0 + c * 16u, Xrow + c * 4);
        asm volatile("cp.async.commit_group;");

        #pragma unroll
        for (int qr = 0; qr < 4; qr++) qv[qr] = QWp[(size_t)qr * N_DIM];
        s = SCp[0];

        // dequant tile0 -> Bs buf0
        #pragma unroll
        for (int qr = 0; qr < 4; qr++) {
            const uint32_t q = (uint32_t)qv[qr];
            #pragma unroll
            for (int j = 0; j < 8; j++) {
                float fv = __uint_as_float(0x4B000000u | ((q >> (4 * j)) & 15u));
                Bs[(qr * 8 + j) * BS_STRIDE + tid] =
                    rn_tf32((fv - 8388616.0f) * s);
            }
        }
        asm volatile("cp.async.wait_group 0;" ::: "memory");
        __syncthreads();
    }

    // ---- main loop -----------------------------------------------------------
    for (int iter = 0; iter < K_ITERS; iter++) {
        const int buf = iter & 1;
        const int nb  = buf ^ 1;
        const bool more = (iter + 1 < K_ITERS);

        // stage next tile: A via cp.async, B qweights via LDG into regs
        if (more) {
            const int k0n = (iter + 1) * BK;
            const float* xp = Xrow + k0n;
            const uint32_t ad = a_dst0 + (uint32_t)(nb * A_ELEMS) * 4u;
            #pragma unroll
            for (int c = 0; c < 4; c++)
                cp16(ad + c * 16u, xp + c * 4);
            asm volatile("cp.async.commit_group;");

            const int krow = k0n >> 3;
            #pragma unroll
            for (int qr = 0; qr < 4; qr++)
                qv[qr] = QWp[(size_t)(krow + qr) * N_DIM];
            s = SCp[(size_t)(k0n >> 7) * N_DIM];
        }

        // ---- compute on current buffer, frag loads pipelined across kk -------
        {
            const float* Asb = As + buf * A_ELEMS + (wm * 64 + g) * AS_STRIDE + t;
            const float* Bsb = Bs + buf * B_ELEMS + t * BS_STRIDE + wn * 64 + g;

            uint32_t af[2][4][4], bf[2][8][2];

            // load frags for kk = 0
            #pragma unroll
            for (int i = 0; i < 4; i++) {
                const float* ar = Asb + i * 16 * AS_STRIDE;
                af[0][i][0] = __float_as_uint(ar[0]);
                af[0][i][1] = __float_as_uint(ar[8 * AS_STRIDE]);
                af[0][i][2] = __float_as_uint(ar[4]);
                af[0][i][3] = __float_as_uint(ar[8 * AS_STRIDE + 4]);
            }
            #pragma unroll
            for (int j = 0; j < 8; j++) {
                const float* br = Bsb + j * 8;
                bf[0][j][0] = __float_as_uint(br[0]);
                bf[0][j][1] = __float_as_uint(br[4 * BS_STRIDE]);
            }

            #pragma unroll
            for (int kk = 0; kk < 4; kk++) {
                const int cur = kk & 1;
                const int nxt = cur ^ 1;
                if (kk < 3) {
                    const int kb = (kk + 1) * 8;
                    #pragma unroll
                    for (int i = 0; i < 4; i++) {
                        const float* ar = Asb + i * 16 * AS_STRIDE + kb;
                        af[nxt][i][0] = __float_as_uint(ar[0]);
                        af[nxt][i][1] = __float_as_uint(ar[8 * AS_STRIDE]);
                        af[nxt][i][2] = __float_as_uint(ar[4]);
                        af[nxt][i][3] = __float_as_uint(ar[8 * AS_STRIDE + 4]);
                    }
                    #pragma unroll
                    for (int j = 0; j < 8; j++) {
                        const float* br = Bsb + kb * BS_STRIDE + j * 8;
                        bf[nxt][j][0] = __float_as_uint(br[0]);
                        bf[nxt][j][1] = __float_as_uint(br[4 * BS_STRIDE]);
                    }
                }
                #pragma unroll
                for (int i = 0; i < 4; i++)
                    #pragma unroll
                    for (int j = 0; j < 8; j++)
                        mma_tf32(acc[i][j],
                                 af[cur][i][0], af[cur][i][1],
                                 af[cur][i][2], af[cur][i][3],
                                 bf[cur][j][0], bf[cur][j][1]);
            }
        }

        // ---- dequant next B tile into the other buffer ------------------------
        if (more) {
            float* Bn = Bs + nb * B_ELEMS;
            #pragma unroll
            for (int qr = 0; qr < 4; qr++) {
                const uint32_t q = (uint32_t)qv[qr];
                #pragma unroll
                for (int j = 0; j < 8; j++) {
                    float fv = __uint_as_float(0x4B000000u | ((q >> (4 * j)) & 15u));
                    Bn[(qr * 8 + j) * BS_STRIDE + tid] =
                        rn_tf32((fv - 8388616.0f) * s);
                }
            }
            asm volatile("cp.async.wait_group 0;" ::: "memory");
        }
        __syncthreads();
    }

    // ---- writeback (m16n8k8 C layout) ----------------------------------------
    #pragma unroll
    for (int i = 0; i < 4; i++) {
        int row = m0 + wm * 64 + i * 16 + g;
        #pragma unroll
        for (int j = 0; j < 8; j++) {
            int col = n0 + wn * 64 + j * 8 + 2 * t;
            *reinterpret_cast<float2*>(&C[(size_t)row * N_DIM + col]) =
                make_float2(acc[i][j][0], acc[i][j][1]);
            *reinterpret_cast<float2*>(&C[(size_t)(row + 8) * N_DIM + col]) =
                make_float2(acc[i][j][2], acc[i][j][3]);
        }
    }
}

extern "C" void kernel_launch(void* const* d_in, const int* in_sizes, int n_in,
                              void* d_out, int out_size)
{
    const float* x   = (const float*)d_in[0];
    const int*   qw  = (const int*)d_in[1];
    const float* sc  = (const float*)d_in[2];
    float*       out = (float*)d_out;

    cudaFuncSetAttribute(int4_gemm_tf32_db_kernel,
                         cudaFuncAttributeMaxDynamicSharedMemorySize, SMEM_BYTES);

    dim3 grid(N_DIM / BN, M_DIM / BM);  // (43, 64)
    int4_gemm_tf32_db_kernel<<<grid, NTH, SMEM_BYTES>>>(x, qw, sc, out);
}